// round 1
// baseline (speedup 1.0000x reference)
#include <cuda_runtime.h>
#include <math.h>

#define D_MODEL   1024
#define NUM_HEADS 16
#define HEAD_DIM  64
#define BATCH     2
#define SEQ       2048
#define MROWS     (BATCH*SEQ)   /* 4096 */

// ---------------------------------------------------------------------------
// Scratch (allocation-free: __device__ globals)
// ---------------------------------------------------------------------------
__device__ float g_Q[MROWS * D_MODEL];
__device__ float g_K[MROWS * D_MODEL];
__device__ float g_V[MROWS * D_MODEL];
__device__ float g_AO[MROWS * D_MODEL];

// ---------------------------------------------------------------------------
// GEMM core: C[M=4096, N=1024] = A[4096,1024] @ W[1024,1024]^T   (fp32)
// Block tile 128x128, K-tile 16, 256 threads, 8x8 per thread.
// ---------------------------------------------------------------------------
__device__ __forceinline__ void gemm_core(const float* __restrict__ A,
                                          const float* __restrict__ W,
                                          float* __restrict__ C)
{
    __shared__ float As[16][128];
    __shared__ float Bs[16][128];

    const int tid = threadIdx.x;
    const int tx  = tid & 15;       // 0..15 -> N direction
    const int ty  = tid >> 4;       // 0..15 -> M direction
    const int m0  = blockIdx.y * 128;
    const int n0  = blockIdx.x * 128;

    float acc[8][8];
#pragma unroll
    for (int i = 0; i < 8; i++)
#pragma unroll
        for (int j = 0; j < 8; j++) acc[i][j] = 0.0f;

    for (int k0 = 0; k0 < D_MODEL; k0 += 16) {
        // cooperative loads: 128 rows x 16 cols each for A and W, transposed into smem
#pragma unroll
        for (int l = 0; l < 2; l++) {
            int id  = tid + l * 256;          // 0..511 float4 slots
            int row = id >> 2;                // 0..127
            int c4  = (id & 3) * 4;           // 0,4,8,12
            float4 av = *(const float4*)&A[(size_t)(m0 + row) * D_MODEL + k0 + c4];
            As[c4 + 0][row] = av.x;
            As[c4 + 1][row] = av.y;
            As[c4 + 2][row] = av.z;
            As[c4 + 3][row] = av.w;
            float4 bv = *(const float4*)&W[(size_t)(n0 + row) * D_MODEL + k0 + c4];
            Bs[c4 + 0][row] = bv.x;
            Bs[c4 + 1][row] = bv.y;
            Bs[c4 + 2][row] = bv.z;
            Bs[c4 + 3][row] = bv.w;
        }
        __syncthreads();

#pragma unroll
        for (int k = 0; k < 16; k++) {
            float a[8], b[8];
            *(float4*)&a[0] = *(const float4*)&As[k][ty * 8 + 0];
            *(float4*)&a[4] = *(const float4*)&As[k][ty * 8 + 4];
            *(float4*)&b[0] = *(const float4*)&Bs[k][tx * 8 + 0];
            *(float4*)&b[4] = *(const float4*)&Bs[k][tx * 8 + 4];
#pragma unroll
            for (int i = 0; i < 8; i++)
#pragma unroll
                for (int j = 0; j < 8; j++)
                    acc[i][j] += a[i] * b[j];
        }
        __syncthreads();
    }

#pragma unroll
    for (int i = 0; i < 8; i++) {
        size_t roff = (size_t)(m0 + ty * 8 + i) * D_MODEL + n0 + tx * 8;
        float4 v0 = make_float4(acc[i][0], acc[i][1], acc[i][2], acc[i][3]);
        float4 v1 = make_float4(acc[i][4], acc[i][5], acc[i][6], acc[i][7]);
        *(float4*)&C[roff + 0] = v0;
        *(float4*)&C[roff + 4] = v1;
    }
}

__global__ void qkv_gemm_kernel(const float* __restrict__ X,
                                const float* __restrict__ Wq,
                                const float* __restrict__ Wk,
                                const float* __restrict__ Wv)
{
    const float* W = (blockIdx.z == 0) ? Wq : (blockIdx.z == 1) ? Wk : Wv;
    float* C       = (blockIdx.z == 0) ? g_Q : (blockIdx.z == 1) ? g_K : g_V;
    gemm_core(X, W, C);
}

__global__ void o_gemm_kernel(const float* __restrict__ Wo,
                              float* __restrict__ out)
{
    gemm_core(g_AO, Wo, out);
}

// ---------------------------------------------------------------------------
// RoPE (in-place on g_Q / g_K).  One thread per even/odd pair.
// ---------------------------------------------------------------------------
__global__ void rope_kernel(const int* __restrict__ pos)
{
    int p = blockIdx.x * blockDim.x + threadIdx.x;   // pair id within tensor
    if (p >= MROWS * (D_MODEL / 2)) return;
    float* buf = (blockIdx.y == 0) ? g_Q : g_K;

    int row = p >> 9;          // / 512 pairs per row
    int e2  = p & 511;         // pair index within row
    int s   = row & (SEQ - 1); // row = b*SEQ + s
    int i   = e2 & 31;         // freq index within head (HEAD_DIM/2 = 32)

    // inv_freq = 10000^(-i/32), computed in double then rounded (<=0.5 ulp)
    float inv_freq = (float)exp(-(double)i * (9.210340371976184 / 32.0));
    float ang = (float)pos[s] * inv_freq;
    float sn, cs;
    sincosf(ang, &sn, &cs);

    size_t off = (size_t)row * D_MODEL + (size_t)e2 * 2;
    float xe = buf[off], xo = buf[off + 1];
    buf[off]     = xe * cs - xo * sn;
    buf[off + 1] = xe * sn + xo * cs;
}

// ---------------------------------------------------------------------------
// Causal flash attention, fp32.
//   grid: (SEQ/128, BATCH*NUM_HEADS), 128 threads, 1 thread = 1 query row.
//   Key tile = 32; scores staged in padded smem; online softmax.
// ---------------------------------------------------------------------------
#define BM   128
#define BKEY 32

__global__ void attn_kernel()
{
    __shared__ float Ks[BKEY * HEAD_DIM];        // 8 KB
    __shared__ float Vs[BKEY * HEAD_DIM];        // 8 KB
    __shared__ float Sc[BM * (BKEY + 1)];        // 16.5 KB (padded)

    const int tid = threadIdx.x;
    const int bh  = blockIdx.y;
    const int b   = bh >> 4;
    const int h   = bh & 15;
    const int m0  = blockIdx.x * BM;
    const int qi  = m0 + tid;

    const float* __restrict__ Kbase = g_K + (size_t)b * SEQ * D_MODEL + h * HEAD_DIM;
    const float* __restrict__ Vbase = g_V + (size_t)b * SEQ * D_MODEL + h * HEAD_DIM;
    const float* __restrict__ qptr  = g_Q + (size_t)(b * SEQ + qi) * D_MODEL + h * HEAD_DIM;

    float q[HEAD_DIM];
#pragma unroll
    for (int d4 = 0; d4 < 16; d4++)
        *(float4*)&q[d4 * 4] = *(const float4*)&qptr[d4 * 4];

    float acc[HEAD_DIM];
#pragma unroll
    for (int d = 0; d < HEAD_DIM; d++) acc[d] = 0.0f;
    float m_i = -1e30f;
    float l   = 0.0f;

    const int kend = m0 + BM;   // keys < kend (max query in block + 1)

    for (int kt = 0; kt < kend; kt += BKEY) {
        // cooperative K/V tile load: 32 rows x 64 cols = 2048 floats each
#pragma unroll
        for (int it = 0; it < 4; it++) {
            int v  = tid + it * 128;       // 0..511 float4 slots
            int j  = v >> 4;               // 0..31
            int d4 = (v & 15) * 4;         // 0..60
            *(float4*)&Ks[j * HEAD_DIM + d4] =
                *(const float4*)&Kbase[(size_t)(kt + j) * D_MODEL + d4];
            *(float4*)&Vs[j * HEAD_DIM + d4] =
                *(const float4*)&Vbase[(size_t)(kt + j) * D_MODEL + d4];
        }
        __syncthreads();

        // --- scores ---
        float tmax = -1e30f;
#pragma unroll 4
        for (int j = 0; j < BKEY; j++) {
            float s0 = 0.f, s1 = 0.f, s2 = 0.f, s3 = 0.f;
            const float4* kr = (const float4*)&Ks[j * HEAD_DIM];
#pragma unroll
            for (int d4 = 0; d4 < 16; d4++) {
                float4 kv = kr[d4];
                s0 += q[d4 * 4 + 0] * kv.x;
                s1 += q[d4 * 4 + 1] * kv.y;
                s2 += q[d4 * 4 + 2] * kv.z;
                s3 += q[d4 * 4 + 3] * kv.w;
            }
            float s = (kt + j <= qi) ? (s0 + s1 + s2 + s3) * 0.125f : -1e30f;
            Sc[tid * (BKEY + 1) + j] = s;
            tmax = fmaxf(tmax, s);
        }

        // --- online softmax rescale ---
        float m_new = fmaxf(m_i, tmax);
        float corr  = __expf(m_i - m_new);
        l *= corr;
#pragma unroll
        for (int d = 0; d < HEAD_DIM; d++) acc[d] *= corr;
        m_i = m_new;

        // --- P @ V ---
#pragma unroll 4
        for (int j = 0; j < BKEY; j++) {
            float p = __expf(Sc[tid * (BKEY + 1) + j] - m_i);
            l += p;
            const float4* vr = (const float4*)&Vs[j * HEAD_DIM];
#pragma unroll
            for (int d4 = 0; d4 < 16; d4++) {
                float4 vv = vr[d4];
                acc[d4 * 4 + 0] += p * vv.x;
                acc[d4 * 4 + 1] += p * vv.y;
                acc[d4 * 4 + 2] += p * vv.z;
                acc[d4 * 4 + 3] += p * vv.w;
            }
        }
        __syncthreads();
    }

    float inv_l = 1.0f / l;
    float* op = g_AO + (size_t)(b * SEQ + qi) * D_MODEL + h * HEAD_DIM;
#pragma unroll
    for (int d4 = 0; d4 < 16; d4++) {
        float4 v = make_float4(acc[d4 * 4 + 0] * inv_l, acc[d4 * 4 + 1] * inv_l,
                               acc[d4 * 4 + 2] * inv_l, acc[d4 * 4 + 3] * inv_l);
        *(float4*)&op[d4 * 4] = v;
    }
}

// ---------------------------------------------------------------------------
// Launch
// Inputs: 0=in_features(f32 [2,2048,1024]) 1=q_proj 2=k_proj 3=v_proj
//         4=o_proj (f32 [1024,1024])       5=token_positions(i32 [2048])
// Output: f32 [2,2048,1024]
// ---------------------------------------------------------------------------
extern "C" void kernel_launch(void* const* d_in, const int* in_sizes, int n_in,
                              void* d_out, int out_size)
{
    const float* X   = (const float*)d_in[0];
    const float* Wq  = (const float*)d_in[1];
    const float* Wk  = (const float*)d_in[2];
    const float* Wv  = (const float*)d_in[3];
    const float* Wo  = (const float*)d_in[4];
    const int*   pos = (const int*)d_in[5];
    float* out = (float*)d_out;

    // 1) QKV projections
    dim3 ggrid(D_MODEL / 128, MROWS / 128, 3);
    qkv_gemm_kernel<<<ggrid, 256>>>(X, Wq, Wk, Wv);

    // 2) RoPE on Q and K
    int pairs = MROWS * (D_MODEL / 2);
    dim3 rgrid((pairs + 255) / 256, 2);
    rope_kernel<<<rgrid, 256>>>(pos);

    // 3) causal attention
    dim3 agrid(SEQ / BM, BATCH * NUM_HEADS);
    attn_kernel<<<agrid, BM>>>();

    // 4) output projection
    dim3 ogrid(D_MODEL / 128, MROWS / 128, 1);
    o_gemm_kernel<<<ogrid, 256>>>(Wo, out);
}

// round 3
// speedup vs baseline: 1.4601x; 1.4601x over previous
#include <cuda_runtime.h>
#include <math.h>
#include <stdint.h>

#define D_MODEL   1024
#define NUM_HEADS 16
#define HEAD_DIM  64
#define BATCH     2
#define SEQ       2048
#define MROWS     (BATCH*SEQ)   /* 4096 */

// ---------------------------------------------------------------------------
// Scratch (allocation-free: __device__ globals)
// ---------------------------------------------------------------------------
__device__ float g_Q[MROWS * D_MODEL];
__device__ float g_K[MROWS * D_MODEL];
__device__ float g_V[MROWS * D_MODEL];
__device__ float g_AO[MROWS * D_MODEL];

// ---------------------------------------------------------------------------
// helpers
// ---------------------------------------------------------------------------
__device__ __forceinline__ uint32_t smem_u32(const void* p) {
    uint32_t a;
    asm("{ .reg .u64 t; cvta.to.shared.u64 t, %1; cvt.u32.u64 %0, t; }" : "=r"(a) : "l"(p));
    return a;
}
__device__ __forceinline__ uint32_t f2tf32(float f) {
    uint32_t r;
    asm("cvt.rna.tf32.f32 %0, %1;" : "=r"(r) : "f"(f));
    return r;
}
__device__ __forceinline__ void cpasync16(uint32_t s, const void* g) {
    asm volatile("cp.async.ca.shared.global [%0], [%1], 16;" :: "r"(s), "l"(g) : "memory");
}
__device__ __forceinline__ void cp_commit() {
    asm volatile("cp.async.commit_group;" ::: "memory");
}
__device__ __forceinline__ void cp_wait1() {
    asm volatile("cp.async.wait_group 1;" ::: "memory");
}
__device__ __forceinline__ void cp_wait0() {
    asm volatile("cp.async.wait_group 0;" ::: "memory");
}

__device__ __forceinline__ void mma_tf32(float c[4], uint32_t a0, uint32_t a1,
                                         uint32_t a2, uint32_t a3,
                                         uint32_t b0, uint32_t b1) {
    asm volatile(
        "mma.sync.aligned.m16n8k8.row.col.f32.tf32.tf32.f32 "
        "{%0,%1,%2,%3}, {%4,%5,%6,%7}, {%8,%9}, {%0,%1,%2,%3};"
        : "+f"(c[0]), "+f"(c[1]), "+f"(c[2]), "+f"(c[3])
        : "r"(a0), "r"(a1), "r"(a2), "r"(a3), "r"(b0), "r"(b1));
}

// ---------------------------------------------------------------------------
// tf32 mma.sync GEMM core: C[M,1024] = A[M,1024] @ W[1024,1024]^T
// CTA tile 128x128, BK=16, 256 threads (warp grid 2x4, warp tile 64x32).
// cp.async double-buffered smem, stride-20 padding (conflict-free frags).
// ---------------------------------------------------------------------------
#define BK       16
#define ASTRIDE  20
#define NTILES   (D_MODEL / BK)   /* 64 */

__device__ __forceinline__ void gemm_mma_core(const float* __restrict__ A,
                                              const float* __restrict__ W,
                                              float* __restrict__ C)
{
    __shared__ __align__(16) float As[2][128 * ASTRIDE];
    __shared__ __align__(16) float Bs[2][128 * ASTRIDE];

    const int tid   = threadIdx.x;
    const int lane  = tid & 31;
    const int wid   = tid >> 5;
    const int warpM = wid & 1;      // 2 warps along M
    const int warpN = wid >> 1;     // 4 warps along N
    const int gid   = lane >> 2;    // 0..7
    const int tig   = lane & 3;     // 0..3
    const int m0    = blockIdx.y * 128;
    const int n0    = blockIdx.x * 128;

    const uint32_t sA[2] = { smem_u32(As[0]), smem_u32(As[1]) };
    const uint32_t sB[2] = { smem_u32(Bs[0]), smem_u32(Bs[1]) };

    // cp.async slot geometry (512 float4 slots per matrix per tile)
    const int r0 = tid >> 2;              // rows for slot 0 / slot 1
    const int r1 = (tid + 256) >> 2;
    const int c4 = (tid & 3) * 4;         // float offset within row

    float acc[4][4][4];
#pragma unroll
    for (int i = 0; i < 4; i++)
#pragma unroll
        for (int j = 0; j < 4; j++)
#pragma unroll
            for (int q = 0; q < 4; q++) acc[i][j][q] = 0.0f;

    // prefetch tile 0
    {
        cpasync16(sA[0] + (uint32_t)(r0 * ASTRIDE + c4) * 4, &A[(size_t)(m0 + r0) * D_MODEL + c4]);
        cpasync16(sB[0] + (uint32_t)(r0 * ASTRIDE + c4) * 4, &W[(size_t)(n0 + r0) * D_MODEL + c4]);
        cpasync16(sA[0] + (uint32_t)(r1 * ASTRIDE + c4) * 4, &A[(size_t)(m0 + r1) * D_MODEL + c4]);
        cpasync16(sB[0] + (uint32_t)(r1 * ASTRIDE + c4) * 4, &W[(size_t)(n0 + r1) * D_MODEL + c4]);
        cp_commit();
    }

    int buf = 0;
    for (int t = 0; t < NTILES; t++) {
        if (t + 1 < NTILES) {
            const int k0 = (t + 1) * BK;
            const int nb = buf ^ 1;
            cpasync16(sA[nb] + (uint32_t)(r0 * ASTRIDE + c4) * 4, &A[(size_t)(m0 + r0) * D_MODEL + k0 + c4]);
            cpasync16(sB[nb] + (uint32_t)(r0 * ASTRIDE + c4) * 4, &W[(size_t)(n0 + r0) * D_MODEL + k0 + c4]);
            cpasync16(sA[nb] + (uint32_t)(r1 * ASTRIDE + c4) * 4, &A[(size_t)(m0 + r1) * D_MODEL + k0 + c4]);
            cpasync16(sB[nb] + (uint32_t)(r1 * ASTRIDE + c4) * 4, &W[(size_t)(n0 + r1) * D_MODEL + k0 + c4]);
            cp_commit();
            cp_wait1();
        } else {
            cp_wait0();
        }
        __syncthreads();

        const float* At = As[buf];
        const float* Bt = Bs[buf];
#pragma unroll
        for (int ks = 0; ks < 2; ks++) {
            const int k0 = ks * 8;
            uint32_t af[4][4], bf[4][2];
#pragma unroll
            for (int mf = 0; mf < 4; mf++) {
                const int ra = warpM * 64 + mf * 16 + gid;
                af[mf][0] = f2tf32(At[ra * ASTRIDE + k0 + tig]);
                af[mf][1] = f2tf32(At[(ra + 8) * ASTRIDE + k0 + tig]);
                af[mf][2] = f2tf32(At[ra * ASTRIDE + k0 + tig + 4]);
                af[mf][3] = f2tf32(At[(ra + 8) * ASTRIDE + k0 + tig + 4]);
            }
#pragma unroll
            for (int nf = 0; nf < 4; nf++) {
                const int rb = warpN * 32 + nf * 8 + gid;
                bf[nf][0] = f2tf32(Bt[rb * ASTRIDE + k0 + tig]);
                bf[nf][1] = f2tf32(Bt[rb * ASTRIDE + k0 + tig + 4]);
            }
#pragma unroll
            for (int mf = 0; mf < 4; mf++)
#pragma unroll
                for (int nf = 0; nf < 4; nf++)
                    mma_tf32(acc[mf][nf], af[mf][0], af[mf][1], af[mf][2], af[mf][3],
                             bf[nf][0], bf[nf][1]);
        }
        __syncthreads();
        buf ^= 1;
    }

    // epilogue: each thread owns (row, 2*tig) pairs -> float2 stores
#pragma unroll
    for (int mf = 0; mf < 4; mf++) {
#pragma unroll
        for (int nf = 0; nf < 4; nf++) {
            const int r = m0 + warpM * 64 + mf * 16 + gid;
            const int c = n0 + warpN * 32 + nf * 8 + 2 * tig;
            float2 v0 = make_float2(acc[mf][nf][0], acc[mf][nf][1]);
            float2 v1 = make_float2(acc[mf][nf][2], acc[mf][nf][3]);
            *(float2*)&C[(size_t)r * D_MODEL + c] = v0;
            *(float2*)&C[(size_t)(r + 8) * D_MODEL + c] = v1;
        }
    }
}

__global__ void __launch_bounds__(256)
qkv_gemm_kernel(const float* __restrict__ X,
                const float* __restrict__ Wq,
                const float* __restrict__ Wk,
                const float* __restrict__ Wv)
{
    const float* W = (blockIdx.z == 0) ? Wq : (blockIdx.z == 1) ? Wk : Wv;
    float* C       = (blockIdx.z == 0) ? g_Q : (blockIdx.z == 1) ? g_K : g_V;
    gemm_mma_core(X, W, C);
}

__global__ void __launch_bounds__(256)
o_gemm_kernel(const float* __restrict__ Wo, float* __restrict__ out)
{
    gemm_mma_core(g_AO, Wo, out);
}

// ---------------------------------------------------------------------------
// RoPE (in-place on g_Q / g_K).  One thread per even/odd pair.
// ---------------------------------------------------------------------------
__global__ void rope_kernel(const int* __restrict__ pos)
{
    int p = blockIdx.x * blockDim.x + threadIdx.x;
    if (p >= MROWS * (D_MODEL / 2)) return;
    float* buf = (blockIdx.y == 0) ? g_Q : g_K;

    int row = p >> 9;
    int e2  = p & 511;
    int s   = row & (SEQ - 1);
    int i   = e2 & 31;

    float inv_freq = (float)exp(-(double)i * (9.210340371976184 / 32.0));
    float ang = (float)pos[s] * inv_freq;
    float sn, cs;
    sincosf(ang, &sn, &cs);

    size_t off = (size_t)row * D_MODEL + (size_t)e2 * 2;
    float xe = buf[off], xo = buf[off + 1];
    buf[off]     = xe * cs - xo * sn;
    buf[off + 1] = xe * sn + xo * cs;
}

// ---------------------------------------------------------------------------
// Causal flash attention, fp32 (unchanged this round).
// ---------------------------------------------------------------------------
#define BM   128
#define BKEY 32

__global__ void attn_kernel()
{
    __shared__ float Ks[BKEY * HEAD_DIM];
    __shared__ float Vs[BKEY * HEAD_DIM];
    __shared__ float Sc[BM * (BKEY + 1)];

    const int tid = threadIdx.x;
    const int bh  = blockIdx.y;
    const int b   = bh >> 4;
    const int h   = bh & 15;
    const int m0  = blockIdx.x * BM;
    const int qi  = m0 + tid;

    const float* __restrict__ Kbase = g_K + (size_t)b * SEQ * D_MODEL + h * HEAD_DIM;
    const float* __restrict__ Vbase = g_V + (size_t)b * SEQ * D_MODEL + h * HEAD_DIM;
    const float* __restrict__ qptr  = g_Q + (size_t)(b * SEQ + qi) * D_MODEL + h * HEAD_DIM;

    float q[HEAD_DIM];
#pragma unroll
    for (int d4 = 0; d4 < 16; d4++)
        *(float4*)&q[d4 * 4] = *(const float4*)&qptr[d4 * 4];

    float acc[HEAD_DIM];
#pragma unroll
    for (int d = 0; d < HEAD_DIM; d++) acc[d] = 0.0f;
    float m_i = -1e30f;
    float l   = 0.0f;

    const int kend = m0 + BM;

    for (int kt = 0; kt < kend; kt += BKEY) {
#pragma unroll
        for (int it = 0; it < 4; it++) {
            int v  = tid + it * 128;
            int j  = v >> 4;
            int d4 = (v & 15) * 4;
            *(float4*)&Ks[j * HEAD_DIM + d4] =
                *(const float4*)&Kbase[(size_t)(kt + j) * D_MODEL + d4];
            *(float4*)&Vs[j * HEAD_DIM + d4] =
                *(const float4*)&Vbase[(size_t)(kt + j) * D_MODEL + d4];
        }
        __syncthreads();

        float tmax = -1e30f;
#pragma unroll 4
        for (int j = 0; j < BKEY; j++) {
            float s0 = 0.f, s1 = 0.f, s2 = 0.f, s3 = 0.f;
            const float4* kr = (const float4*)&Ks[j * HEAD_DIM];
#pragma unroll
            for (int d4 = 0; d4 < 16; d4++) {
                float4 kv = kr[d4];
                s0 += q[d4 * 4 + 0] * kv.x;
                s1 += q[d4 * 4 + 1] * kv.y;
                s2 += q[d4 * 4 + 2] * kv.z;
                s3 += q[d4 * 4 + 3] * kv.w;
            }
            float s = (kt + j <= qi) ? (s0 + s1 + s2 + s3) * 0.125f : -1e30f;
            Sc[tid * (BKEY + 1) + j] = s;
            tmax = fmaxf(tmax, s);
        }

        float m_new = fmaxf(m_i, tmax);
        float corr  = __expf(m_i - m_new);
        l *= corr;
#pragma unroll
        for (int d = 0; d < HEAD_DIM; d++) acc[d] *= corr;
        m_i = m_new;

#pragma unroll 4
        for (int j = 0; j < BKEY; j++) {
            float p = __expf(Sc[tid * (BKEY + 1) + j] - m_i);
            l += p;
            const float4* vr = (const float4*)&Vs[j * HEAD_DIM];
#pragma unroll
            for (int d4 = 0; d4 < 16; d4++) {
                float4 vv = vr[d4];
                acc[d4 * 4 + 0] += p * vv.x;
                acc[d4 * 4 + 1] += p * vv.y;
                acc[d4 * 4 + 2] += p * vv.z;
                acc[d4 * 4 + 3] += p * vv.w;
            }
        }
        __syncthreads();
    }

    float inv_l = 1.0f / l;
    float* op = g_AO + (size_t)(b * SEQ + qi) * D_MODEL + h * HEAD_DIM;
#pragma unroll
    for (int d4 = 0; d4 < 16; d4++) {
        float4 v = make_float4(acc[d4 * 4 + 0] * inv_l, acc[d4 * 4 + 1] * inv_l,
                               acc[d4 * 4 + 2] * inv_l, acc[d4 * 4 + 3] * inv_l);
        *(float4*)&op[d4 * 4] = v;
    }
}

// ---------------------------------------------------------------------------
// Launch
// ---------------------------------------------------------------------------
extern "C" void kernel_launch(void* const* d_in, const int* in_sizes, int n_in,
                              void* d_out, int out_size)
{
    const float* X   = (const float*)d_in[0];
    const float* Wq  = (const float*)d_in[1];
    const float* Wk  = (const float*)d_in[2];
    const float* Wv  = (const float*)d_in[3];
    const float* Wo  = (const float*)d_in[4];
    const int*   pos = (const int*)d_in[5];
    float* out = (float*)d_out;

    // 1) QKV projections (tf32 mma.sync)
    dim3 ggrid(D_MODEL / 128, MROWS / 128, 3);
    qkv_gemm_kernel<<<ggrid, 256>>>(X, Wq, Wk, Wv);

    // 2) RoPE on Q and K
    int pairs = MROWS * (D_MODEL / 2);
    dim3 rgrid((pairs + 255) / 256, 2);
    rope_kernel<<<rgrid, 256>>>(pos);

    // 3) causal attention (fp32)
    dim3 agrid(SEQ / BM, BATCH * NUM_HEADS);
    attn_kernel<<<agrid, BM>>>();

    // 4) output projection (tf32 mma.sync)
    dim3 ogrid(D_MODEL / 128, MROWS / 128, 1);
    o_gemm_kernel<<<ogrid, 256>>>(Wo, out);
}

// round 4
// speedup vs baseline: 2.7742x; 1.9000x over previous
#include <cuda_runtime.h>
#include <math.h>
#include <stdint.h>

#define D_MODEL   1024
#define NUM_HEADS 16
#define HEAD_DIM  64
#define BATCH     2
#define SEQ       2048
#define MROWS     (BATCH*SEQ)   /* 4096 */

// ---------------------------------------------------------------------------
// Scratch (allocation-free: __device__ globals)
// ---------------------------------------------------------------------------
__device__ float g_Q[MROWS * D_MODEL];
__device__ float g_K[MROWS * D_MODEL];
__device__ float g_V[MROWS * D_MODEL];
__device__ float g_AO[MROWS * D_MODEL];

// ---------------------------------------------------------------------------
// helpers
// ---------------------------------------------------------------------------
__device__ __forceinline__ uint32_t smem_u32(const void* p) {
    uint32_t a;
    asm("{ .reg .u64 t; cvta.to.shared.u64 t, %1; cvt.u32.u64 %0, t; }" : "=r"(a) : "l"(p));
    return a;
}
__device__ __forceinline__ uint32_t f2tf32(float f) {
    uint32_t r;
    asm("cvt.rna.tf32.f32 %0, %1;" : "=r"(r) : "f"(f));
    return r;
}
__device__ __forceinline__ void cpasync16(uint32_t s, const void* g) {
    asm volatile("cp.async.ca.shared.global [%0], [%1], 16;" :: "r"(s), "l"(g) : "memory");
}
__device__ __forceinline__ void cp_commit() { asm volatile("cp.async.commit_group;" ::: "memory"); }
__device__ __forceinline__ void cp_wait1()  { asm volatile("cp.async.wait_group 1;" ::: "memory"); }
__device__ __forceinline__ void cp_wait0()  { asm volatile("cp.async.wait_group 0;" ::: "memory"); }

__device__ __forceinline__ void mma_tf32(float c[4], uint32_t a0, uint32_t a1,
                                         uint32_t a2, uint32_t a3,
                                         uint32_t b0, uint32_t b1) {
    asm volatile(
        "mma.sync.aligned.m16n8k8.row.col.f32.tf32.tf32.f32 "
        "{%0,%1,%2,%3}, {%4,%5,%6,%7}, {%8,%9}, {%0,%1,%2,%3};"
        : "+f"(c[0]), "+f"(c[1]), "+f"(c[2]), "+f"(c[3])
        : "r"(a0), "r"(a1), "r"(a2), "r"(a3), "r"(b0), "r"(b1));
}

// ---------------------------------------------------------------------------
// tf32 mma.sync GEMM core (unchanged from round 3)
// ---------------------------------------------------------------------------
#define BK       16
#define ASTRIDE  20
#define NTILES   (D_MODEL / BK)   /* 64 */

__device__ __forceinline__ void gemm_mma_core(const float* __restrict__ A,
                                              const float* __restrict__ W,
                                              float* __restrict__ C)
{
    __shared__ __align__(16) float As[2][128 * ASTRIDE];
    __shared__ __align__(16) float Bs[2][128 * ASTRIDE];

    const int tid   = threadIdx.x;
    const int lane  = tid & 31;
    const int wid   = tid >> 5;
    const int warpM = wid & 1;
    const int warpN = wid >> 1;
    const int gid   = lane >> 2;
    const int tig   = lane & 3;
    const int m0    = blockIdx.y * 128;
    const int n0    = blockIdx.x * 128;

    const uint32_t sA[2] = { smem_u32(As[0]), smem_u32(As[1]) };
    const uint32_t sB[2] = { smem_u32(Bs[0]), smem_u32(Bs[1]) };

    const int r0 = tid >> 2;
    const int r1 = (tid + 256) >> 2;
    const int c4 = (tid & 3) * 4;

    float acc[4][4][4];
#pragma unroll
    for (int i = 0; i < 4; i++)
#pragma unroll
        for (int j = 0; j < 4; j++)
#pragma unroll
            for (int q = 0; q < 4; q++) acc[i][j][q] = 0.0f;

    cpasync16(sA[0] + (uint32_t)(r0 * ASTRIDE + c4) * 4, &A[(size_t)(m0 + r0) * D_MODEL + c4]);
    cpasync16(sB[0] + (uint32_t)(r0 * ASTRIDE + c4) * 4, &W[(size_t)(n0 + r0) * D_MODEL + c4]);
    cpasync16(sA[0] + (uint32_t)(r1 * ASTRIDE + c4) * 4, &A[(size_t)(m0 + r1) * D_MODEL + c4]);
    cpasync16(sB[0] + (uint32_t)(r1 * ASTRIDE + c4) * 4, &W[(size_t)(n0 + r1) * D_MODEL + c4]);
    cp_commit();

    int buf = 0;
    for (int t = 0; t < NTILES; t++) {
        if (t + 1 < NTILES) {
            const int k0 = (t + 1) * BK;
            const int nb = buf ^ 1;
            cpasync16(sA[nb] + (uint32_t)(r0 * ASTRIDE + c4) * 4, &A[(size_t)(m0 + r0) * D_MODEL + k0 + c4]);
            cpasync16(sB[nb] + (uint32_t)(r0 * ASTRIDE + c4) * 4, &W[(size_t)(n0 + r0) * D_MODEL + k0 + c4]);
            cpasync16(sA[nb] + (uint32_t)(r1 * ASTRIDE + c4) * 4, &A[(size_t)(m0 + r1) * D_MODEL + k0 + c4]);
            cpasync16(sB[nb] + (uint32_t)(r1 * ASTRIDE + c4) * 4, &W[(size_t)(n0 + r1) * D_MODEL + k0 + c4]);
            cp_commit();
            cp_wait1();
        } else {
            cp_wait0();
        }
        __syncthreads();

        const float* At = As[buf];
        const float* Bt = Bs[buf];
#pragma unroll
        for (int ks = 0; ks < 2; ks++) {
            const int k0 = ks * 8;
            uint32_t af[4][4], bf[4][2];
#pragma unroll
            for (int mf = 0; mf < 4; mf++) {
                const int ra = warpM * 64 + mf * 16 + gid;
                af[mf][0] = f2tf32(At[ra * ASTRIDE + k0 + tig]);
                af[mf][1] = f2tf32(At[(ra + 8) * ASTRIDE + k0 + tig]);
                af[mf][2] = f2tf32(At[ra * ASTRIDE + k0 + tig + 4]);
                af[mf][3] = f2tf32(At[(ra + 8) * ASTRIDE + k0 + tig + 4]);
            }
#pragma unroll
            for (int nf = 0; nf < 4; nf++) {
                const int rb = warpN * 32 + nf * 8 + gid;
                bf[nf][0] = f2tf32(Bt[rb * ASTRIDE + k0 + tig]);
                bf[nf][1] = f2tf32(Bt[rb * ASTRIDE + k0 + tig + 4]);
            }
#pragma unroll
            for (int mf = 0; mf < 4; mf++)
#pragma unroll
                for (int nf = 0; nf < 4; nf++)
                    mma_tf32(acc[mf][nf], af[mf][0], af[mf][1], af[mf][2], af[mf][3],
                             bf[nf][0], bf[nf][1]);
        }
        __syncthreads();
        buf ^= 1;
    }

#pragma unroll
    for (int mf = 0; mf < 4; mf++) {
#pragma unroll
        for (int nf = 0; nf < 4; nf++) {
            const int r = m0 + warpM * 64 + mf * 16 + gid;
            const int c = n0 + warpN * 32 + nf * 8 + 2 * tig;
            float2 v0 = make_float2(acc[mf][nf][0], acc[mf][nf][1]);
            float2 v1 = make_float2(acc[mf][nf][2], acc[mf][nf][3]);
            *(float2*)&C[(size_t)r * D_MODEL + c] = v0;
            *(float2*)&C[(size_t)(r + 8) * D_MODEL + c] = v1;
        }
    }
}

__global__ void __launch_bounds__(256)
qkv_gemm_kernel(const float* __restrict__ X,
                const float* __restrict__ Wq,
                const float* __restrict__ Wk,
                const float* __restrict__ Wv)
{
    const float* W = (blockIdx.z == 0) ? Wq : (blockIdx.z == 1) ? Wk : Wv;
    float* C       = (blockIdx.z == 0) ? g_Q : (blockIdx.z == 1) ? g_K : g_V;
    gemm_mma_core(X, W, C);
}

__global__ void __launch_bounds__(256)
o_gemm_kernel(const float* __restrict__ Wo, float* __restrict__ out)
{
    gemm_mma_core(g_AO, Wo, out);
}

// ---------------------------------------------------------------------------
// RoPE (in-place on g_Q / g_K)
// ---------------------------------------------------------------------------
__global__ void rope_kernel(const int* __restrict__ pos)
{
    int p = blockIdx.x * blockDim.x + threadIdx.x;
    if (p >= MROWS * (D_MODEL / 2)) return;
    float* buf = (blockIdx.y == 0) ? g_Q : g_K;

    int row = p >> 9;
    int e2  = p & 511;
    int s   = row & (SEQ - 1);
    int i   = e2 & 31;

    float inv_freq = (float)exp(-(double)i * (9.210340371976184 / 32.0));
    float ang = (float)pos[s] * inv_freq;
    float sn, cs;
    sincosf(ang, &sn, &cs);

    size_t off = (size_t)row * D_MODEL + (size_t)e2 * 2;
    float xe = buf[off], xo = buf[off + 1];
    buf[off]     = xe * cs - xo * sn;
    buf[off + 1] = xe * sn + xo * cs;
}

// ---------------------------------------------------------------------------
// Causal flash attention with m16n8k8 tf32 mma.
//   grid (SEQ/128, BATCH*NUM_HEADS), 256 threads (8 warps x 16 q-rows).
//   Key tile 64. S=Q@K^T on tensor cores, online softmax in fragments,
//   P staged through smem (tf32 bits), O=P@V on tensor cores (V transposed).
// ---------------------------------------------------------------------------
#define A_BM  128
#define A_BN  64
#define A_STR 68                       /* stride in u32: 68 mod 32 = 4 -> conflict-free frags */
#define ATT_SMEM ((A_BN*A_STR + HEAD_DIM*A_STR + A_BM*A_STR) * 4)   /* 69632 B */

extern __shared__ uint32_t att_smem[];

__global__ void __launch_bounds__(256)
attn_mma_kernel()
{
    uint32_t* Ks = att_smem;                     // [64][68]  tf32 bits, K-major
    uint32_t* Vt = Ks + A_BN * A_STR;            // [64][68]  tf32 bits, transposed: Vt[dim][key]
    uint32_t* Ps = Vt + HEAD_DIM * A_STR;        // [128][68] tf32 bits, P row-major

    const int tid  = threadIdx.x;
    const int lane = tid & 31;
    const int w    = tid >> 5;       // 0..7
    const int gid  = lane >> 2;      // 0..7
    const int tig  = lane & 3;       // 0..3
    const int bh   = blockIdx.y;
    const int b    = bh >> 4;
    const int h    = bh & 15;
    const int m0   = blockIdx.x * A_BM;

    const float* __restrict__ Qb = g_Q + (size_t)b * SEQ * D_MODEL + h * HEAD_DIM;
    const float* __restrict__ Kb = g_K + (size_t)b * SEQ * D_MODEL + h * HEAD_DIM;
    const float* __restrict__ Vb = g_V + (size_t)b * SEQ * D_MODEL + h * HEAD_DIM;

    const int r0 = m0 + w * 16 + gid;    // this thread's two query rows
    const int r1 = r0 + 8;

    // Q fragments, pre-scaled by 1/sqrt(HEAD_DIM) (exact pow2, no extra rounding)
    uint32_t qf[8][4];
#pragma unroll
    for (int kc = 0; kc < 8; kc++) {
        qf[kc][0] = f2tf32(0.125f * Qb[(size_t)r0 * D_MODEL + kc * 8 + tig]);
        qf[kc][1] = f2tf32(0.125f * Qb[(size_t)r1 * D_MODEL + kc * 8 + tig]);
        qf[kc][2] = f2tf32(0.125f * Qb[(size_t)r0 * D_MODEL + kc * 8 + tig + 4]);
        qf[kc][3] = f2tf32(0.125f * Qb[(size_t)r1 * D_MODEL + kc * 8 + tig + 4]);
    }

    float oacc[8][4];
#pragma unroll
    for (int nf = 0; nf < 8; nf++)
#pragma unroll
        for (int q = 0; q < 4; q++) oacc[nf][q] = 0.0f;
    float m_a = -1e30f, m_b = -1e30f, l_a = 0.0f, l_b = 0.0f;

    const int kend = m0 + A_BM;

    for (int kt = 0; kt < kend; kt += A_BN) {
        if (kt > 0) __syncthreads();   // previous O-mma must finish reading Ks/Vt

        // --- cooperative loads (fp32 -> tf32 bits in smem) ---
        // K tile [64 keys][64 dims], coalesced
#pragma unroll
        for (int it = 0; it < 4; it++) {
            int id  = tid + it * 256;
            int row = id >> 4;
            int c4  = (id & 15) * 4;
            float4 v = *(const float4*)&Kb[(size_t)(kt + row) * D_MODEL + c4];
            uint32_t* d = &Ks[row * A_STR + c4];
            asm volatile("st.shared.v4.b32 [%0], {%1,%2,%3,%4};"
                :: "r"(smem_u32(d)), "r"(f2tf32(v.x)), "r"(f2tf32(v.y)),
                   "r"(f2tf32(v.z)), "r"(f2tf32(v.w)) : "memory");
        }
        // V tile transposed: Vt[dim][key]
#pragma unroll
        for (int it = 0; it < 4; it++) {
            int id = tid + it * 256;
            int j  = id & 63;          // key
            int d4 = (id >> 6) * 4;    // dim base
            float4 v = *(const float4*)&Vb[(size_t)(kt + j) * D_MODEL + d4];
            Vt[(d4 + 0) * A_STR + j] = f2tf32(v.x);
            Vt[(d4 + 1) * A_STR + j] = f2tf32(v.y);
            Vt[(d4 + 2) * A_STR + j] = f2tf32(v.z);
            Vt[(d4 + 3) * A_STR + j] = f2tf32(v.w);
        }
        __syncthreads();

        // --- S = Q @ K^T ---
        float sacc[8][4];
#pragma unroll
        for (int nf = 0; nf < 8; nf++)
#pragma unroll
            for (int q = 0; q < 4; q++) sacc[nf][q] = 0.0f;

#pragma unroll
        for (int kc = 0; kc < 8; kc++) {
            uint32_t bf[8][2];
#pragma unroll
            for (int nf = 0; nf < 8; nf++) {
                const int rb = nf * 8 + gid;
                bf[nf][0] = Ks[rb * A_STR + kc * 8 + tig];
                bf[nf][1] = Ks[rb * A_STR + kc * 8 + tig + 4];
            }
#pragma unroll
            for (int nf = 0; nf < 8; nf++)
                mma_tf32(sacc[nf], qf[kc][0], qf[kc][1], qf[kc][2], qf[kc][3],
                         bf[nf][0], bf[nf][1]);
        }

        // --- causal mask (only needed on the last two tiles) ---
        if (kt + A_BN - 1 > m0) {
#pragma unroll
            for (int nf = 0; nf < 8; nf++) {
                int c = kt + nf * 8 + 2 * tig;
                if (c > r0)     sacc[nf][0] = -1e30f;
                if (c + 1 > r0) sacc[nf][1] = -1e30f;
                if (c > r1)     sacc[nf][2] = -1e30f;
                if (c + 1 > r1) sacc[nf][3] = -1e30f;
            }
        }

        // --- online softmax ---
        float mx_a = -1e30f, mx_b = -1e30f;
#pragma unroll
        for (int nf = 0; nf < 8; nf++) {
            mx_a = fmaxf(mx_a, fmaxf(sacc[nf][0], sacc[nf][1]));
            mx_b = fmaxf(mx_b, fmaxf(sacc[nf][2], sacc[nf][3]));
        }
        mx_a = fmaxf(mx_a, __shfl_xor_sync(0xFFFFFFFFu, mx_a, 1));
        mx_a = fmaxf(mx_a, __shfl_xor_sync(0xFFFFFFFFu, mx_a, 2));
        mx_b = fmaxf(mx_b, __shfl_xor_sync(0xFFFFFFFFu, mx_b, 1));
        mx_b = fmaxf(mx_b, __shfl_xor_sync(0xFFFFFFFFu, mx_b, 2));

        const float mna = fmaxf(m_a, mx_a);
        const float mnb = fmaxf(m_b, mx_b);
        const float ca  = __expf(m_a - mna);
        const float cb  = __expf(m_b - mnb);
        m_a = mna; m_b = mnb;

        float sa = 0.0f, sb = 0.0f;
#pragma unroll
        for (int nf = 0; nf < 8; nf++) {
            sacc[nf][0] = __expf(sacc[nf][0] - mna);
            sacc[nf][1] = __expf(sacc[nf][1] - mna);
            sacc[nf][2] = __expf(sacc[nf][2] - mnb);
            sacc[nf][3] = __expf(sacc[nf][3] - mnb);
            sa += sacc[nf][0] + sacc[nf][1];
            sb += sacc[nf][2] + sacc[nf][3];
        }
        sa += __shfl_xor_sync(0xFFFFFFFFu, sa, 1);
        sa += __shfl_xor_sync(0xFFFFFFFFu, sa, 2);
        sb += __shfl_xor_sync(0xFFFFFFFFu, sb, 1);
        sb += __shfl_xor_sync(0xFFFFFFFFu, sb, 2);
        l_a = l_a * ca + sa;
        l_b = l_b * cb + sb;
#pragma unroll
        for (int nf = 0; nf < 8; nf++) {
            oacc[nf][0] *= ca; oacc[nf][1] *= ca;
            oacc[nf][2] *= cb; oacc[nf][3] *= cb;
        }

        // --- stage P (tf32 bits) to smem; warp-private rows ---
        const int pr0 = w * 16 + gid;
#pragma unroll
        for (int nf = 0; nf < 8; nf++) {
            int c = nf * 8 + 2 * tig;
            asm volatile("st.shared.v2.b32 [%0], {%1,%2};"
                :: "r"(smem_u32(&Ps[pr0 * A_STR + c])),
                   "r"(f2tf32(sacc[nf][0])), "r"(f2tf32(sacc[nf][1])) : "memory");
            asm volatile("st.shared.v2.b32 [%0], {%1,%2};"
                :: "r"(smem_u32(&Ps[(pr0 + 8) * A_STR + c])),
                   "r"(f2tf32(sacc[nf][2])), "r"(f2tf32(sacc[nf][3])) : "memory");
        }
        __syncwarp();

        // --- O += P @ V ---
#pragma unroll
        for (int kc = 0; kc < 8; kc++) {
            uint32_t a0 = Ps[pr0 * A_STR + kc * 8 + tig];
            uint32_t a1 = Ps[(pr0 + 8) * A_STR + kc * 8 + tig];
            uint32_t a2 = Ps[pr0 * A_STR + kc * 8 + tig + 4];
            uint32_t a3 = Ps[(pr0 + 8) * A_STR + kc * 8 + tig + 4];
            uint32_t bf[8][2];
#pragma unroll
            for (int nf = 0; nf < 8; nf++) {
                const int rb = nf * 8 + gid;
                bf[nf][0] = Vt[rb * A_STR + kc * 8 + tig];
                bf[nf][1] = Vt[rb * A_STR + kc * 8 + tig + 4];
            }
#pragma unroll
            for (int nf = 0; nf < 8; nf++)
                mma_tf32(oacc[nf], a0, a1, a2, a3, bf[nf][0], bf[nf][1]);
        }
    }

    // --- final normalize + store ---
    const float ila = 1.0f / l_a;
    const float ilb = 1.0f / l_b;
    float* oa = g_AO + (size_t)(b * SEQ + r0) * D_MODEL + h * HEAD_DIM;
    float* ob = g_AO + (size_t)(b * SEQ + r1) * D_MODEL + h * HEAD_DIM;
#pragma unroll
    for (int nf = 0; nf < 8; nf++) {
        int c = nf * 8 + 2 * tig;
        *(float2*)&oa[c] = make_float2(oacc[nf][0] * ila, oacc[nf][1] * ila);
        *(float2*)&ob[c] = make_float2(oacc[nf][2] * ilb, oacc[nf][3] * ilb);
    }
}

// ---------------------------------------------------------------------------
// Launch
// ---------------------------------------------------------------------------
extern "C" void kernel_launch(void* const* d_in, const int* in_sizes, int n_in,
                              void* d_out, int out_size)
{
    const float* X   = (const float*)d_in[0];
    const float* Wq  = (const float*)d_in[1];
    const float* Wk  = (const float*)d_in[2];
    const float* Wv  = (const float*)d_in[3];
    const float* Wo  = (const float*)d_in[4];
    const int*   pos = (const int*)d_in[5];
    float* out = (float*)d_out;

    static int attr_set = 0;
    if (!attr_set) {
        cudaFuncSetAttribute(attn_mma_kernel,
                             cudaFuncAttributeMaxDynamicSharedMemorySize, ATT_SMEM);
        attr_set = 1;
    }

    // 1) QKV projections (tf32 mma.sync)
    dim3 ggrid(D_MODEL / 128, MROWS / 128, 3);
    qkv_gemm_kernel<<<ggrid, 256>>>(X, Wq, Wk, Wv);

    // 2) RoPE on Q and K
    int pairs = MROWS * (D_MODEL / 2);
    dim3 rgrid((pairs + 255) / 256, 2);
    rope_kernel<<<rgrid, 256>>>(pos);

    // 3) causal attention (tf32 mma.sync)
    dim3 agrid(SEQ / A_BM, BATCH * NUM_HEADS);
    attn_mma_kernel<<<agrid, 256, ATT_SMEM>>>();

    // 4) output projection (tf32 mma.sync)
    dim3 ogrid(D_MODEL / 128, MROWS / 128, 1);
    o_gemm_kernel<<<ogrid, 256>>>(Wo, out);
}